// round 8
// baseline (speedup 1.0000x reference)
#include <cuda_runtime.h>

// ArcFace loss, two-kernel structure with PDL overlap (+ safe fallback):
//   tgt[i]   = wf[i, labels[i]]
//   num[i]   = S*(t*cosM - sqrt(1-t^2)*sinM)     (== S*cos(acos(clip t)+M))
//   excl[i]  = sum_j exp(S*wf[i,j]) - exp(S*tgt[i])
//   L[i]     = num[i] - log(exp(num[i]) + excl[i])
//   out      = -mean(L)
//
// wf: [B=8192, C=10000] fp32 (327.7 MB, HBM-bound single pass)
// labels: [B] int32 (harness downcasts int64 indices)
//
// R7: PDL confirmed working (54.2us). R8 additions:
//  - target gather (labels[row], p[lbl]) prefetched BEFORE the mainloop so
//    its ~600cy latency hides under the stream instead of extending each
//    CTA's tail (~2us aggregate at oe=8).
//  - explicit cudaTriggerProgrammaticLaunchCompletion() after the g_L store:
//    dependent grid can proceed at last-block trigger, not grid teardown.

#define MAX_B 16384

static __device__ float g_L[MAX_B];

#define SCALE 64.0f
#define COS_M 0.8775825618903728f   // cos(0.5)
#define SIN_M 0.479425538604203f    // sin(0.5)
#define EPSC  1e-7f

// ---------- Row kernel ----------
__global__ __launch_bounds__(256) void arcface_row_kernel(
    const float* __restrict__ wf,
    const int* __restrict__ labels,
    int C)
{
    const int row = blockIdx.x;
    const float* __restrict__ p = wf + (size_t)row * (size_t)C;

    // Prefetch the target gather on thread 0 BEFORE the streaming loop.
    // Independent loads; the scoreboard parks them until the epilogue.
    float t_pref = 0.0f;
    if (threadIdx.x == 0) {
        int lbl = labels[row];
        lbl = max(0, min(lbl, C - 1));           // defensive clamp
        t_pref = p[lbl];
    }

    float acc = 0.0f;

    // Vectorized main path (C % 4 == 0: 10000 = 2500 * 4).
    // __ldcs: read-once stream, evict-first.
    const int n4 = C >> 2;
    const float4* __restrict__ p4 = (const float4*)p;
    for (int i = threadIdx.x; i < n4; i += 256) {
        float4 v = __ldcs(&p4[i]);
        acc += __expf(SCALE * v.x);
        acc += __expf(SCALE * v.y);
        acc += __expf(SCALE * v.z);
        acc += __expf(SCALE * v.w);
    }
    // Scalar tail (empty when C % 4 == 0)
    for (int i = (n4 << 2) + threadIdx.x; i < C; i += 256) {
        acc += __expf(SCALE * p[i]);
    }

    // Block reduction: warp shuffle then smem across 8 warps
    #pragma unroll
    for (int o = 16; o > 0; o >>= 1)
        acc += __shfl_down_sync(0xffffffffu, acc, o);

    __shared__ float warp_sums[8];
    const int lane = threadIdx.x & 31;
    const int wid  = threadIdx.x >> 5;
    if (lane == 0) warp_sums[wid] = acc;
    __syncthreads();

    if (threadIdx.x == 0) {
        float s = 0.0f;
        #pragma unroll
        for (int i = 0; i < 8; i++) s += warp_sums[i];

        const float t = t_pref;                  // already in flight/register
        float tc = fminf(fmaxf(t, -1.0f + EPSC), 1.0f - EPSC);
        float num = SCALE * (tc * COS_M - sqrtf(fmaxf(1.0f - tc * tc, 0.0f)) * SIN_M);
        float excl = s - __expf(SCALE * t);
        float denom = __expf(num) + excl;
        g_L[row] = num - __logf(denom);

        // Signal the dependent grid now; block exit/teardown is off the path.
        cudaTriggerProgrammaticLaunchCompletion();
    }
}

// ---------- Shared reduce body ----------
__device__ __forceinline__ void reduce_body(float* __restrict__ out, int B)
{
    const int n4 = B >> 2;
    const float4* __restrict__ p4 = (const float4*)g_L;

    float acc = 0.0f;
    for (int i = threadIdx.x; i < n4; i += 256) {
        float4 v = p4[i];
        acc += v.x + v.y + v.z + v.w;
    }
    for (int i = (n4 << 2) + threadIdx.x; i < B; i += 256)
        acc += g_L[i];

    #pragma unroll
    for (int o = 16; o > 0; o >>= 1)
        acc += __shfl_down_sync(0xffffffffu, acc, o);

    __shared__ float warp_sums[8];
    const int lane = threadIdx.x & 31;
    const int wid  = threadIdx.x >> 5;
    if (lane == 0) warp_sums[wid] = acc;
    __syncthreads();

    if (threadIdx.x == 0) {
        float total = 0.0f;
        #pragma unroll
        for (int i = 0; i < 8; i++) total += warp_sums[i];
        out[0] = -total / (float)B;
    }
}

// PDL variant: waits on the prior grid via the dependency trigger.
__global__ __launch_bounds__(256) void arcface_reduce_pdl(float* __restrict__ out, int B)
{
    cudaGridDependencySynchronize();
    reduce_body(out, B);
}

// Plain variant: ordinary stream ordering provides the dependency.
__global__ __launch_bounds__(256) void arcface_reduce_plain(float* __restrict__ out, int B)
{
    reduce_body(out, B);
}

extern "C" void kernel_launch(void* const* d_in, const int* in_sizes, int n_in,
                              void* d_out, int out_size)
{
    const float* wf     = (const float*)d_in[0];
    const int*   labels = (const int*)d_in[1];
    float*       out    = (float*)d_out;

    const int B = in_sizes[1];               // 8192
    const int C = in_sizes[0] / B;           // 10000

    arcface_row_kernel<<<B, 256>>>(wf, labels, C);

    // PDL-attributed secondary: may begin (grid setup + preamble) while the
    // row kernel runs; cudaGridDependencySynchronize() inside provides the
    // ordering. Fall back to a plain launch if the attributed launch is
    // rejected.
    cudaLaunchAttribute attr[1];
    attr[0].id = cudaLaunchAttributeProgrammaticStreamSerialization;
    attr[0].val.programmaticStreamSerializationAllowed = 1;

    cudaLaunchConfig_t cfg = {};
    cfg.gridDim  = dim3(1, 1, 1);
    cfg.blockDim = dim3(256, 1, 1);
    cfg.dynamicSmemBytes = 0;
    cfg.stream   = 0;                        // legacy default stream (captured)
    cfg.attrs    = attr;
    cfg.numAttrs = 1;

    cudaError_t e = cudaLaunchKernelEx(&cfg, arcface_reduce_pdl, out, B);
    if (e != cudaSuccess) {
        (void)cudaGetLastError();            // clear sticky error
        arcface_reduce_plain<<<1, 256>>>(out, B);
    }
}